// round 16
// baseline (speedup 1.0000x reference)
#include <cuda_runtime.h>
#include <cuda_bf16.h>
#include <math.h>
#include <float.h>
#include <stdint.h>

// Problem constants
#define CB_SIZE 8192
#define CB_DIM  128
#define IN_DIM  1024
#define NROWS   32768   // B*N = 8*4096

typedef unsigned long long ull;

// ---------------- packed fp32x2 helpers (projection kernel) ----------------
#define FMA2(acc, a, b) \
    asm("fma.rn.f32x2 %0, %1, %2, %0;" : "+l"(acc) : "l"(a), "l"(b))
#define PACKDUP(d, s) \
    asm("mov.b64 %0, {%1, %1};" : "=l"(d) : "f"(s))
#define UNPACK2(lo, hi, p) \
    asm("mov.b64 {%0, %1}, %2;" : "=f"(lo), "=f"(hi) : "l"(p))

// ---------------- cp.async helpers (Ampere+ base PTX, sm_103-legal) --------
#define CPA16(dst, src) \
    asm volatile("cp.async.cg.shared.global [%0], [%1], 16;" :: "r"(dst), "l"(src) : "memory")
#define CP_COMMIT() asm volatile("cp.async.commit_group;" ::: "memory")
#define CP_WAIT1()  asm volatile("cp.async.wait_group 1;" ::: "memory")
#define CP_WAIT0()  asm volatile("cp.async.wait_group 0;" ::: "memory")

__device__ __forceinline__ uint32_t smem_u32(const void* p) {
    uint32_t a;
    asm("{ .reg .u64 t; cvta.to.shared.u64 t, %1; cvt.u32.u64 %0, t; }" : "=r"(a) : "l"(p));
    return a;
}

// ---------------- scratch globals (allocation-free rule) ----------------
__device__ float g_nx [NROWS  * CB_DIM];      // projected+normalized rows (f32)
__device__ float g_ncb[CB_SIZE * CB_DIM];     // normalized codebook (f32)
__device__ float g_h2 [CB_SIZE];              // 0.5*||ncb||^2
__device__ float g_nal[NROWS];                // ||lo-split|| per nx row
__device__ int   g_mbl;                       // max ||lo-split|| over codes (f32 bits)
__device__ __nv_bfloat16 g_afh[NROWS  * CB_DIM];  // A hi frags (phase A)
__device__ __nv_bfloat16 g_bfh[CB_SIZE * CB_DIM]; // B hi frags
__device__ __nv_bfloat16 g_bfl[CB_SIZE * CB_DIM]; // B lo frags
__device__ int g_nflag,  g_flag [NROWS];      // phase-A flags
__device__ int g_nflagB, g_flagB[NROWS];      // phase-B flags

#define GAP_THR_B 2e-4f    // phase-B certification (3-product err << this)

// ---------------------------------------------------------------------------
// Kernel 1: normalize codebook rows; emit h2; write B fragments (hi+lo);
// atomicMax of ||bl|| per code into g_mbl. Resets flag counters.
// One warp per code.
// ---------------------------------------------------------------------------
__global__ void rpq_prep_cb(const float* __restrict__ cb) {
    int gtid = blockIdx.x * blockDim.x + threadIdx.x;
    if (gtid == 0) { g_nflag = 0; g_nflagB = 0; }
    int code = gtid >> 5;
    int lane = gtid & 31;
    if (code >= CB_SIZE) return;

    const float4* src = (const float4*)(cb + (size_t)code * CB_DIM);
    float4 v = src[lane];
    float s = v.x*v.x + v.y*v.y + v.z*v.z + v.w*v.w;
    #pragma unroll
    for (int o = 16; o > 0; o >>= 1) s += __shfl_xor_sync(0xffffffffu, s, o);
    float inv = 1.0f / fmaxf(sqrtf(s), 1e-12f);
    float4 nv = make_float4(v.x*inv, v.y*inv, v.z*inv, v.w*inv);
    float s2 = nv.x*nv.x + nv.y*nv.y + nv.z*nv.z + nv.w*nv.w;
    #pragma unroll
    for (int o = 16; o > 0; o >>= 1) s2 += __shfl_xor_sync(0xffffffffu, s2, o);
    ((float4*)(g_ncb + (size_t)code * CB_DIM))[lane] = nv;
    if (lane == 0) g_h2[code] = 0.5f * s2;

    // fragment split writes + ||bl||^2
    float vv[4] = {nv.x, nv.y, nv.z, nv.w};
    float blsq = 0.0f;
    int u = code >> 6, n = code & 63;
    int f = n >> 3, gg = n & 7;
    #pragma unroll
    for (int e4 = 0; e4 < 4; e4++) {
        int k = lane * 4 + e4;
        float val = vv[e4];
        __nv_bfloat16 h = __float2bfloat16(val);
        __nv_bfloat16 l = __float2bfloat16(val - __bfloat162float(h));
        float lf = __bfloat162float(l);
        blsq += lf * lf;
        int ks = k >> 4, rk = k & 15;
        int q = (rk & 7) >> 1, e = rk & 1, kh = rk >> 3;
        size_t fidx = ((size_t)u * 8192) + (size_t)(((ks*8 + f)*32 + gg*4 + q)*4 + kh*2 + e);
        g_bfh[fidx] = h;
        g_bfl[fidx] = l;
    }
    #pragma unroll
    for (int o = 16; o > 0; o >>= 1) blsq += __shfl_xor_sync(0xffffffffu, blsq, o);
    if (lane == 0) atomicMax(&g_mbl, __float_as_int(sqrtf(blsq)));
}

// ---------------------------------------------------------------------------
// Kernel 2: projection GEMM (FFMA2) + row normalize + A-hi fragment split
// + per-row ||al|| — all fused. Block = 128 rows (one fragment tile).
// ---------------------------------------------------------------------------
#define PJ_BK 32
#define PJ_PAD 132

__global__ __launch_bounds__(256, 2) void rpq_proj_fused(
    const float* __restrict__ X, const float* __restrict__ W)
{
    __shared__ float As[PJ_BK][PJ_PAD];
    __shared__ float Bs[PJ_BK][PJ_PAD];
    int tid = threadIdx.x, tr = tid >> 4, tc = tid & 15;
    int rowbase = blockIdx.x * 128;

    ull acc[4][8];
    #pragma unroll
    for (int p = 0; p < 4; p++)
        #pragma unroll
        for (int j = 0; j < 8; j++) acc[p][j] = 0ull;

    for (int k0 = 0; k0 < IN_DIM; k0 += PJ_BK) {
        #pragma unroll
        for (int q = 0; q < 4; q++) {
            int id = tid + 256 * q, m = id >> 3, kk = (id & 7) << 2;
            float4 v = *(const float4*)(X + (size_t)(rowbase + m) * IN_DIM + k0 + kk);
            As[kk+0][m] = v.x; As[kk+1][m] = v.y; As[kk+2][m] = v.z; As[kk+3][m] = v.w;
        }
        #pragma unroll
        for (int q = 0; q < 4; q++) {
            int id = tid + 256 * q, kk = id >> 5, e = (id & 31) << 2;
            *(float4*)&Bs[kk][e] = *(const float4*)(W + (size_t)(k0 + kk) * CB_DIM + e);
        }
        __syncthreads();
        #pragma unroll 8
        for (int kk = 0; kk < PJ_BK; kk++) {
            ull a[4];
            a[0] = *(const ull*)&As[kk][tr*8 + 0];
            a[1] = *(const ull*)&As[kk][tr*8 + 2];
            a[2] = *(const ull*)&As[kk][tr*8 + 4];
            a[3] = *(const ull*)&As[kk][tr*8 + 6];
            float4 b0 = *(float4*)&Bs[kk][tc*8];
            float4 b1 = *(float4*)&Bs[kk][tc*8 + 4];
            ull bb[8];
            PACKDUP(bb[0], b0.x); PACKDUP(bb[1], b0.y);
            PACKDUP(bb[2], b0.z); PACKDUP(bb[3], b0.w);
            PACKDUP(bb[4], b1.x); PACKDUP(bb[5], b1.y);
            PACKDUP(bb[6], b1.z); PACKDUP(bb[7], b1.w);
            #pragma unroll
            for (int p = 0; p < 4; p++)
                #pragma unroll
                for (int j = 0; j < 8; j++)
                    FMA2(acc[p][j], a[p], bb[j]);
        }
        __syncthreads();
    }

    // ---- fused epilogue ----
    float* rs   = &As[0][0];      // 128 x 16 partials (2048 floats)
    float* invs = rs + 2048;      // 128 floats

    // 1) row sum-of-squares partials
    #pragma unroll
    for (int p = 0; p < 4; p++) {
        float slo = 0.0f, shi = 0.0f;
        #pragma unroll
        for (int j = 0; j < 8; j++) {
            float lo, hi; UNPACK2(lo, hi, acc[p][j]);
            slo += lo * lo; shi += hi * hi;
        }
        rs[(tr*8 + 2*p)     * 16 + tc] = slo;
        rs[(tr*8 + 2*p + 1) * 16 + tc] = shi;
    }
    __syncthreads();
    if (tid < 128) {
        float s = 0.0f;
        #pragma unroll
        for (int c = 0; c < 16; c++) s += rs[tid * 16 + c];
        invs[tid] = 1.0f / fmaxf(sqrtf(s), 1e-12f);
    }
    __syncthreads();

    // 2) scale, write g_nx + A-hi fragments, accumulate ||al||^2 partials
    int t = blockIdx.x;
    float alsq[8];
    #pragma unroll
    for (int i = 0; i < 8; i++) alsq[i] = 0.0f;

    #pragma unroll
    for (int p = 0; p < 4; p++) {
        int rl0 = tr*8 + 2*p, rl1 = rl0 + 1;
        float i0 = invs[rl0], i1 = invs[rl1];
        float lov[8], hiv[8];
        #pragma unroll
        for (int j = 0; j < 8; j++) {
            float lo, hi; UNPACK2(lo, hi, acc[p][j]);
            lov[j] = lo * i0; hiv[j] = hi * i1;
        }
        *(float4*)(g_nx + (size_t)(rowbase+rl0)*CB_DIM + tc*8)     = make_float4(lov[0],lov[1],lov[2],lov[3]);
        *(float4*)(g_nx + (size_t)(rowbase+rl0)*CB_DIM + tc*8 + 4) = make_float4(lov[4],lov[5],lov[6],lov[7]);
        *(float4*)(g_nx + (size_t)(rowbase+rl1)*CB_DIM + tc*8)     = make_float4(hiv[0],hiv[1],hiv[2],hiv[3]);
        *(float4*)(g_nx + (size_t)(rowbase+rl1)*CB_DIM + tc*8 + 4) = make_float4(hiv[4],hiv[5],hiv[6],hiv[7]);
        #pragma unroll
        for (int j = 0; j < 8; j++) {
            #pragma unroll
            for (int half = 0; half < 2; half++) {
                int r = half ? rl1 : rl0;
                float val = half ? hiv[j] : lov[j];
                __nv_bfloat16 h = __float2bfloat16(val);
                __nv_bfloat16 l = __float2bfloat16(val - __bfloat162float(h));
                float lf = __bfloat162float(l);
                alsq[2*p + half] += lf * lf;
                int k = tc*8 + j;
                int w = r >> 4, rr = r & 15, gg = rr & 7, half_r = rr >> 3;
                int ks = k >> 4, rk = k & 15;
                int q = (rk & 7) >> 1, e = rk & 1, kh = rk >> 3;
                int slot = half_r + 2*kh;
                size_t fidx = ((size_t)t * 16384) + (size_t)(((w*8 + ks)*32 + gg*4 + q)*8 + slot*2 + e);
                g_afh[fidx] = h;
            }
        }
    }
    // 3) ||al|| per row
    #pragma unroll
    for (int p = 0; p < 4; p++) {
        rs[(tr*8 + 2*p)     * 16 + tc] = alsq[2*p];
        rs[(tr*8 + 2*p + 1) * 16 + tc] = alsq[2*p + 1];
    }
    __syncthreads();
    if (tid < 128) {
        float s = 0.0f;
        #pragma unroll
        for (int c = 0; c < 16; c++) s += rs[tid * 16 + c];
        g_nal[rowbase + tid] = sqrtf(s);
    }
}

// ---------------------------------------------------------------------------
// Shared MMA helper
// ---------------------------------------------------------------------------
__device__ __forceinline__ void mma16816(float c[4], const uint32_t a[4],
                                         const uint32_t b0, const uint32_t b1) {
    asm volatile(
        "mma.sync.aligned.m16n8k16.row.col.f32.bf16.bf16.f32 "
        "{%0,%1,%2,%3}, {%4,%5,%6,%7}, {%8,%9}, {%0,%1,%2,%3};"
        : "+f"(c[0]), "+f"(c[1]), "+f"(c[2]), "+f"(c[3])
        : "r"(a[0]), "r"(a[1]), "r"(a[2]), "r"(a[3]), "r"(b0), "r"(b1));
}

// ---------------------------------------------------------------------------
// Kernel 3 (phase A): hi*hi-only scorer over all rows + certified flagging.
// smem buffer: bh 16384 + h2 256 = 16640; double-buffered (33280 < 48KB).
// ---------------------------------------------------------------------------
#define BUFA 16640

__device__ __forceinline__ void copy_bh_tile(uint32_t dst, int ct, int tid) {
    const char* sh = (const char*)g_bfh + (size_t)ct * 16384;
    const char* hh = (const char*)g_h2  + (size_t)ct * 256;
    for (int i = tid; i < 1040; i += 256) {
        if (i < 1024) CPA16(dst + i * 16,                  sh + i * 16);
        else          CPA16(dst + 16384 + (i - 1024) * 16, hh + (i - 1024) * 16);
    }
    CP_COMMIT();
}

__global__ __launch_bounds__(256, 2) void rpq_scoreA(float* __restrict__ out) {
    extern __shared__ char smem[];
    uint32_t sb = smem_u32(smem);
    int tid  = threadIdx.x;
    int warp = tid >> 5;
    int lane = tid & 31;
    int g    = lane >> 2;
    int t2   = (lane & 3) * 2;
    int rowbase = blockIdx.x * 128;

    uint32_t ah[8][4];
    {
        const uint4* ph = (const uint4*)g_afh + (size_t)blockIdx.x * 2048 + warp * 256 + lane;
        #pragma unroll
        for (int ks = 0; ks < 8; ks++) {
            uint4 v = ph[ks * 32];
            ah[ks][0] = v.x; ah[ks][1] = v.y; ah[ks][2] = v.z; ah[ks][3] = v.w;
        }
    }

    copy_bh_tile(sb, 0, tid);

    float best0 = -FLT_MAX, sb0 = -FLT_MAX, best1 = -FLT_MAX, sb1 = -FLT_MAX;
    int   i0 = 0, i1 = 0;

    for (int ct = 0; ct < 128; ct++) {
        int buf = ct & 1;
        __syncthreads();
        if (ct + 1 < 128) { copy_bh_tile(sb + (buf ^ 1) * BUFA, ct + 1, tid); CP_WAIT1(); }
        else              { CP_WAIT0(); }
        __syncthreads();

        uint32_t bbase = sb + buf * BUFA;
        float c[8][4];
        #pragma unroll
        for (int f = 0; f < 8; f++)
            #pragma unroll
            for (int qq = 0; qq < 4; qq++) c[f][qq] = 0.0f;

        #pragma unroll
        for (int ks = 0; ks < 8; ks++) {
            #pragma unroll
            for (int f = 0; f < 8; f++) {
                uint32_t off = ((ks * 8 + f) * 32 + lane) * 8;
                uint32_t bh0, bh1;
                asm volatile("ld.shared.v2.b32 {%0,%1}, [%2];"
                             : "=r"(bh0), "=r"(bh1) : "r"(bbase + off));
                mma16816(c[f], ah[ks], bh0, bh1);
            }
        }

        const float* h2s = (const float*)(smem + buf * BUFA + 16384);
        int cb0 = ct * 64;
        #pragma unroll
        for (int f = 0; f < 8; f++) {
            float h0 = h2s[f * 8 + t2], h1 = h2s[f * 8 + t2 + 1];
            int id0 = cb0 + f * 8 + t2, id1 = id0 + 1;
            float s;
            s = c[f][0] - h0;
            if (s > best0) { sb0 = best0; best0 = s; i0 = id0; } else if (s > sb0) sb0 = s;
            s = c[f][1] - h1;
            if (s > best0) { sb0 = best0; best0 = s; i0 = id1; } else if (s > sb0) sb0 = s;
            s = c[f][2] - h0;
            if (s > best1) { sb1 = best1; best1 = s; i1 = id0; } else if (s > sb1) sb1 = s;
            s = c[f][3] - h1;
            if (s > best1) { sb1 = best1; best1 = s; i1 = id1; } else if (s > sb1) sb1 = s;
        }
    }

    #pragma unroll
    for (int off = 1; off <= 2; off <<= 1) {
        float ob, osb; int oi;
        ob  = __shfl_xor_sync(0xffffffffu, best0, off);
        osb = __shfl_xor_sync(0xffffffffu, sb0,   off);
        oi  = __shfl_xor_sync(0xffffffffu, i0,    off);
        if (ob > best0) { sb0 = fmaxf(best0, osb); best0 = ob; i0 = oi; }
        else { if (ob == best0 && oi < i0) i0 = oi; sb0 = fmaxf(sb0, ob); }
        ob  = __shfl_xor_sync(0xffffffffu, best1, off);
        osb = __shfl_xor_sync(0xffffffffu, sb1,   off);
        oi  = __shfl_xor_sync(0xffffffffu, i1,    off);
        if (ob > best1) { sb1 = fmaxf(best1, osb); best1 = ob; i1 = oi; }
        else { if (ob == best1 && oi < i1) i1 = oi; sb1 = fmaxf(sb1, ob); }
    }

    if ((lane & 3) == 0) {
        int row0 = rowbase + (warp << 4) + g;
        int row1 = row0 + 8;
        out[row0] = (float)i0;
        out[row1] = (float)i1;
        // certified per-row error bound (Cauchy-Schwarz with computed norms)
        float mbl  = __int_as_float(g_mbl) * 1.002f + 1e-6f;
        float nal0 = g_nal[row0] * 1.002f + 1e-6f;
        float nal1 = g_nal[row1] * 1.002f + 1e-6f;
        float thr0 = 2.0f * (nal0 * (1.001f + 2.0f * mbl) + 1.001f * mbl + 2e-5f);
        float thr1 = 2.0f * (nal1 * (1.001f + 2.0f * mbl) + 1.001f * mbl + 2e-5f);
        if (best0 - sb0 < thr0) { int s = atomicAdd(&g_nflag, 1); g_flag[s] = row0; }
        if (best1 - sb1 < thr1) { int s = atomicAdd(&g_nflag, 1); g_flag[s] = row1; }
    }
}

// ---------------------------------------------------------------------------
// Kernel 4 (phase B): 3-product rescorer on compacted flagged rows.
// Gathers 128 flagged rows, splits+fragments on the fly (smem stage stride
// 129 f32 = 66048 B, reused for double-buffered B tiles 2x33024 = 66048 B).
// ---------------------------------------------------------------------------
#define BUFB 33024
#define SMEM_B2 66048

__device__ __forceinline__ void copy_b_tile(uint32_t dst, int ct, int tid) {
    const char* sh = (const char*)g_bfh + (size_t)ct * 16384;
    const char* sl = (const char*)g_bfl + (size_t)ct * 16384;
    const char* hh = (const char*)g_h2  + (size_t)ct * 256;
    for (int i = tid; i < 2064; i += 256) {
        if (i < 1024)       CPA16(dst + i * 16,                  sh + i * 16);
        else if (i < 2048)  CPA16(dst + 16384 + (i - 1024) * 16, sl + (i - 1024) * 16);
        else                CPA16(dst + 32768 + (i - 2048) * 16, hh + (i - 2048) * 16);
    }
    CP_COMMIT();
}

__device__ __forceinline__ uint32_t packsplit(float v0, float v1, uint32_t* lo) {
    __nv_bfloat16 h0 = __float2bfloat16(v0), h1 = __float2bfloat16(v1);
    __nv_bfloat16 l0 = __float2bfloat16(v0 - __bfloat162float(h0));
    __nv_bfloat16 l1 = __float2bfloat16(v1 - __bfloat162float(h1));
    __nv_bfloat162 hp = __halves2bfloat162(h0, h1);
    __nv_bfloat162 lp = __halves2bfloat162(l0, l1);
    *lo = *reinterpret_cast<uint32_t*>(&lp);
    return *reinterpret_cast<uint32_t*>(&hp);
}

__global__ __launch_bounds__(256, 2) void rpq_scoreB(float* __restrict__ out) {
    extern __shared__ char smem[];
    __shared__ int sidx[128];
    uint32_t sb = smem_u32(smem);
    int tid  = threadIdx.x;
    int warp = tid >> 5;
    int lane = tid & 31;
    int g    = lane >> 2;
    int t2   = (lane & 3) * 2;
    int nf = g_nflag;

    for (int tile = blockIdx.x; tile * 128 < nf; tile += gridDim.x) {
        int cnt = nf - tile * 128; if (cnt > 128) cnt = 128;
        __syncthreads();   // prior iteration's smem fully consumed
        if (tid < 128) sidx[tid] = g_flag[tile * 128 + (tid < cnt ? tid : 0)];
        __syncthreads();

        // stage gathered rows as f32, stride 129 (bank-spread)
        float* stg = (float*)smem;
        for (int i = tid; i < 4096; i += 256) {
            int r = i >> 5, c4 = (i & 31) << 2;
            float4 v = *(const float4*)&g_nx[(size_t)sidx[r] * CB_DIM + c4];
            float* d = stg + r * 129 + c4;
            d[0] = v.x; d[1] = v.y; d[2] = v.z; d[3] = v.w;
        }
        __syncthreads();

        // extract A fragments (hi+lo) to registers
        uint32_t ah[8][4], al[8][4];
        int r0 = (warp << 4) + g;
        #pragma unroll
        for (int ks = 0; ks < 8; ks++) {
            int kb = ks * 16 + t2;
            const float* p00 = stg + r0 * 129 + kb;
            const float* p10 = stg + (r0 + 8) * 129 + kb;
            ah[ks][0] = packsplit(p00[0], p00[1], &al[ks][0]);
            ah[ks][1] = packsplit(p10[0], p10[1], &al[ks][1]);
            ah[ks][2] = packsplit(p00[8], p00[9], &al[ks][2]);
            ah[ks][3] = packsplit(p10[8], p10[9], &al[ks][3]);
        }
        __syncthreads();   // staging reads done before B tiles overwrite

        copy_b_tile(sb, 0, tid);

        float best0 = -FLT_MAX, sb0 = -FLT_MAX, best1 = -FLT_MAX, sb1 = -FLT_MAX;
        int   i0 = 0, i1 = 0;

        for (int ct = 0; ct < 128; ct++) {
            int buf = ct & 1;
            __syncthreads();
            if (ct + 1 < 128) { copy_b_tile(sb + (buf ^ 1) * BUFB, ct + 1, tid); CP_WAIT1(); }
            else              { CP_WAIT0(); }
            __syncthreads();

            uint32_t bbase = sb + buf * BUFB;
            float c[8][4];
            #pragma unroll
            for (int f = 0; f < 8; f++)
                #pragma unroll
                for (int qq = 0; qq < 4; qq++) c[f][qq] = 0.0f;

            #pragma unroll
            for (int ks = 0; ks < 8; ks++) {
                #pragma unroll
                for (int f = 0; f < 8; f++) {
                    uint32_t off = ((ks * 8 + f) * 32 + lane) * 8;
                    uint32_t bh0, bh1, bl0, bl1;
                    asm volatile("ld.shared.v2.b32 {%0,%1}, [%2];"
                                 : "=r"(bh0), "=r"(bh1) : "r"(bbase + off));
                    asm volatile("ld.shared.v2.b32 {%0,%1}, [%2];"
                                 : "=r"(bl0), "=r"(bl1) : "r"(bbase + 16384 + off));
                    mma16816(c[f], ah[ks], bh0, bh1);
                    mma16816(c[f], ah[ks], bl0, bl1);
                    mma16816(c[f], al[ks], bh0, bh1);
                }
            }

            const float* h2s = (const float*)(smem + buf * BUFB + 32768);
            int cb0 = ct * 64;
            #pragma unroll
            for (int f = 0; f < 8; f++) {
                float h0 = h2s[f * 8 + t2], h1 = h2s[f * 8 + t2 + 1];
                int id0 = cb0 + f * 8 + t2, id1 = id0 + 1;
                float s;
                s = c[f][0] - h0;
                if (s > best0) { sb0 = best0; best0 = s; i0 = id0; } else if (s > sb0) sb0 = s;
                s = c[f][1] - h1;
                if (s > best0) { sb0 = best0; best0 = s; i0 = id1; } else if (s > sb0) sb0 = s;
                s = c[f][2] - h0;
                if (s > best1) { sb1 = best1; best1 = s; i1 = id0; } else if (s > sb1) sb1 = s;
                s = c[f][3] - h1;
                if (s > best1) { sb1 = best1; best1 = s; i1 = id1; } else if (s > sb1) sb1 = s;
            }
        }

        #pragma unroll
        for (int off = 1; off <= 2; off <<= 1) {
            float ob, osb; int oi;
            ob  = __shfl_xor_sync(0xffffffffu, best0, off);
            osb = __shfl_xor_sync(0xffffffffu, sb0,   off);
            oi  = __shfl_xor_sync(0xffffffffu, i0,    off);
            if (ob > best0) { sb0 = fmaxf(best0, osb); best0 = ob; i0 = oi; }
            else { if (ob == best0 && oi < i0) i0 = oi; sb0 = fmaxf(sb0, ob); }
            ob  = __shfl_xor_sync(0xffffffffu, best1, off);
            osb = __shfl_xor_sync(0xffffffffu, sb1,   off);
            oi  = __shfl_xor_sync(0xffffffffu, i1,    off);
            if (ob > best1) { sb1 = fmaxf(best1, osb); best1 = ob; i1 = oi; }
            else { if (ob == best1 && oi < i1) i1 = oi; sb1 = fmaxf(sb1, ob); }
        }

        if ((lane & 3) == 0) {
            int pos0 = (warp << 4) + g, pos1 = pos0 + 8;
            if (pos0 < cnt) {
                int row = sidx[pos0];
                out[row] = (float)i0;
                if (best0 - sb0 < GAP_THR_B) { int s = atomicAdd(&g_nflagB, 1); g_flagB[s] = row; }
            }
            if (pos1 < cnt) {
                int row = sidx[pos1];
                out[row] = (float)i1;
                if (best1 - sb1 < GAP_THR_B) { int s = atomicAdd(&g_nflagB, 1); g_flagB[s] = row; }
            }
        }
    }
}

// ---------------------------------------------------------------------------
// Kernel 5 (phase C): exact fp32 rescore of phase-B flagged rows.
// ---------------------------------------------------------------------------
__global__ __launch_bounds__(256) void rpq_exactB(float* __restrict__ out) {
    __shared__ float xr[CB_DIM];
    __shared__ float rb[256];
    __shared__ int   ri[256];
    int tid = threadIdx.x;
    int nf = g_nflagB;
    for (int fi = blockIdx.x; fi < nf; fi += gridDim.x) {
        int row = g_flagB[fi];
        if (tid < CB_DIM) xr[tid] = g_nx[(size_t)row * CB_DIM + tid];
        __syncthreads();
        float best = -FLT_MAX; int bi = 0;
        for (int c = tid; c < CB_SIZE; c += 256) {
            const float* cbr = g_ncb + (size_t)c * CB_DIM;
            float acc = 0.0f;
            #pragma unroll
            for (int k = 0; k < CB_DIM; k += 4) {
                float4 v = *(const float4*)&cbr[k];
                acc = fmaf(v.x, xr[k],     acc);
                acc = fmaf(v.y, xr[k + 1], acc);
                acc = fmaf(v.z, xr[k + 2], acc);
                acc = fmaf(v.w, xr[k + 3], acc);
            }
            float s = acc - g_h2[c];
            if (s > best) { best = s; bi = c; }
        }
        rb[tid] = best; ri[tid] = bi;
        __syncthreads();
        for (int off = 128; off > 0; off >>= 1) {
            if (tid < off) {
                float o = rb[tid + off]; int oi = ri[tid + off];
                if (o > rb[tid] || (o == rb[tid] && oi < ri[tid])) { rb[tid] = o; ri[tid] = oi; }
            }
            __syncthreads();
        }
        if (tid == 0) out[row] = (float)ri[0];
        __syncthreads();
    }
}

// ---------------------------------------------------------------------------
// Launch
// ---------------------------------------------------------------------------
extern "C" void kernel_launch(void* const* d_in, const int* in_sizes, int n_in,
                              void* d_out, int out_size) {
    const float* x  = nullptr;
    const float* W  = nullptr;
    const float* cb = nullptr;
    for (int i = 0; i < n_in; i++) {
        long long s = in_sizes[i];
        if      (s == (long long)NROWS * IN_DIM   || s == (long long)NROWS * IN_DIM * 4)
            x  = (const float*)d_in[i];
        else if (s == (long long)IN_DIM * CB_DIM  || s == (long long)IN_DIM * CB_DIM * 4)
            W  = (const float*)d_in[i];
        else if (s == (long long)CB_SIZE * CB_DIM || s == (long long)CB_SIZE * CB_DIM * 4)
            cb = (const float*)d_in[i];
    }
    if (!x || !W || !cb) {
        x  = (const float*)d_in[0];
        W  = (const float*)d_in[1];
        cb = (const float*)d_in[2];
    }
    float* out = (float*)d_out;

    cudaFuncSetAttribute(rpq_scoreB,
                         cudaFuncAttributeMaxDynamicSharedMemorySize, SMEM_B2);

    rpq_prep_cb  <<<CB_SIZE / 8, 256>>>(cb);
    rpq_proj_fused<<<NROWS / 128, 256>>>(x, W);
    rpq_scoreA   <<<NROWS / 128, 256, 2 * BUFA>>>(out);
    rpq_scoreB   <<<NROWS / 256, 256, SMEM_B2>>>(out);
    rpq_exactB   <<<256, 256>>>(out);
}

// round 17
// speedup vs baseline: 1.1310x; 1.1310x over previous
#include <cuda_runtime.h>
#include <cuda_bf16.h>
#include <math.h>
#include <float.h>
#include <stdint.h>

// Problem constants
#define CB_SIZE 8192
#define CB_DIM  128
#define IN_DIM  1024
#define NROWS   32768   // B*N = 8*4096

typedef unsigned long long ull;

// ---------------- packed fp32x2 helpers (projection kernel) ----------------
#define FMA2(acc, a, b) \
    asm("fma.rn.f32x2 %0, %1, %2, %0;" : "+l"(acc) : "l"(a), "l"(b))
#define PACKDUP(d, s) \
    asm("mov.b64 %0, {%1, %1};" : "=l"(d) : "f"(s))
#define UNPACK2(lo, hi, p) \
    asm("mov.b64 {%0, %1}, %2;" : "=f"(lo), "=f"(hi) : "l"(p))

// ---------------- cp.async helpers (Ampere+ base PTX, sm_103-legal) --------
#define CPA16(dst, src) \
    asm volatile("cp.async.cg.shared.global [%0], [%1], 16;" :: "r"(dst), "l"(src) : "memory")
#define CP_COMMIT() asm volatile("cp.async.commit_group;" ::: "memory")
#define CP_WAIT1()  asm volatile("cp.async.wait_group 1;" ::: "memory")
#define CP_WAIT0()  asm volatile("cp.async.wait_group 0;" ::: "memory")

__device__ __forceinline__ uint32_t smem_u32(const void* p) {
    uint32_t a;
    asm("{ .reg .u64 t; cvta.to.shared.u64 t, %1; cvt.u32.u64 %0, t; }" : "=r"(a) : "l"(p));
    return a;
}

// ---------------- scratch globals (allocation-free rule) ----------------
__device__ float g_nx [NROWS  * CB_DIM];      // projected+normalized rows (f32)
__device__ float g_ncb[CB_SIZE * CB_DIM];     // normalized codebook (f32)
__device__ float g_h2 [CB_SIZE];              // 0.5*||ncb||^2
__device__ float g_nal[NROWS];                // ||lo-split|| per nx row
__device__ int   g_mbl;                       // max ||lo-split|| over codes (f32 bits)
__device__ __nv_bfloat16 g_afh[NROWS  * CB_DIM];  // A hi frags (phase A)
__device__ __nv_bfloat16 g_bfh[CB_SIZE * CB_DIM]; // B hi frags
__device__ __nv_bfloat16 g_bfl[CB_SIZE * CB_DIM]; // B lo frags
__device__ int g_nflag,  g_flag [NROWS];      // phase-A flags
__device__ int g_nflagB, g_flagB[NROWS];      // phase-B flags
// phase-B per-chunk partials: (tile,chunk,pos) -> best/second/idx
#define MAXTILES 256
__device__ float g_pb_b[MAXTILES * 4 * 128];
__device__ float g_pb_s[MAXTILES * 4 * 128];
__device__ int   g_pb_i[MAXTILES * 4 * 128];

#define GAP_THR_B 2e-4f    // phase-B certification (3-product err << this)

// ---------------------------------------------------------------------------
// Kernel 1: normalize codebook rows; emit h2; write B fragments (hi+lo);
// atomicMax of ||bl|| per code into g_mbl. Resets flag counters.
// ---------------------------------------------------------------------------
__global__ void rpq_prep_cb(const float* __restrict__ cb) {
    int gtid = blockIdx.x * blockDim.x + threadIdx.x;
    if (gtid == 0) { g_nflag = 0; g_nflagB = 0; }
    int code = gtid >> 5;
    int lane = gtid & 31;
    if (code >= CB_SIZE) return;

    const float4* src = (const float4*)(cb + (size_t)code * CB_DIM);
    float4 v = src[lane];
    float s = v.x*v.x + v.y*v.y + v.z*v.z + v.w*v.w;
    #pragma unroll
    for (int o = 16; o > 0; o >>= 1) s += __shfl_xor_sync(0xffffffffu, s, o);
    float inv = 1.0f / fmaxf(sqrtf(s), 1e-12f);
    float4 nv = make_float4(v.x*inv, v.y*inv, v.z*inv, v.w*inv);
    float s2 = nv.x*nv.x + nv.y*nv.y + nv.z*nv.z + nv.w*nv.w;
    #pragma unroll
    for (int o = 16; o > 0; o >>= 1) s2 += __shfl_xor_sync(0xffffffffu, s2, o);
    ((float4*)(g_ncb + (size_t)code * CB_DIM))[lane] = nv;
    if (lane == 0) g_h2[code] = 0.5f * s2;

    float vv[4] = {nv.x, nv.y, nv.z, nv.w};
    float blsq = 0.0f;
    int u = code >> 6, n = code & 63;
    int f = n >> 3, gg = n & 7;
    #pragma unroll
    for (int e4 = 0; e4 < 4; e4++) {
        int k = lane * 4 + e4;
        float val = vv[e4];
        __nv_bfloat16 h = __float2bfloat16(val);
        __nv_bfloat16 l = __float2bfloat16(val - __bfloat162float(h));
        float lf = __bfloat162float(l);
        blsq += lf * lf;
        int ks = k >> 4, rk = k & 15;
        int q = (rk & 7) >> 1, e = rk & 1, kh = rk >> 3;
        size_t fidx = ((size_t)u * 8192) + (size_t)(((ks*8 + f)*32 + gg*4 + q)*4 + kh*2 + e);
        g_bfh[fidx] = h;
        g_bfl[fidx] = l;
    }
    #pragma unroll
    for (int o = 16; o > 0; o >>= 1) blsq += __shfl_xor_sync(0xffffffffu, blsq, o);
    if (lane == 0) atomicMax(&g_mbl, __float_as_int(sqrtf(blsq)));
}

// ---------------------------------------------------------------------------
// Kernel 2: projection GEMM (FFMA2) + row normalize + A-hi fragment split
// + per-row ||al|| — all fused. Block = 128 rows.
// ---------------------------------------------------------------------------
#define PJ_BK 32
#define PJ_PAD 132

__global__ __launch_bounds__(256, 2) void rpq_proj_fused(
    const float* __restrict__ X, const float* __restrict__ W)
{
    __shared__ float As[PJ_BK][PJ_PAD];
    __shared__ float Bs[PJ_BK][PJ_PAD];
    int tid = threadIdx.x, tr = tid >> 4, tc = tid & 15;
    int rowbase = blockIdx.x * 128;

    ull acc[4][8];
    #pragma unroll
    for (int p = 0; p < 4; p++)
        #pragma unroll
        for (int j = 0; j < 8; j++) acc[p][j] = 0ull;

    for (int k0 = 0; k0 < IN_DIM; k0 += PJ_BK) {
        #pragma unroll
        for (int q = 0; q < 4; q++) {
            int id = tid + 256 * q, m = id >> 3, kk = (id & 7) << 2;
            float4 v = *(const float4*)(X + (size_t)(rowbase + m) * IN_DIM + k0 + kk);
            As[kk+0][m] = v.x; As[kk+1][m] = v.y; As[kk+2][m] = v.z; As[kk+3][m] = v.w;
        }
        #pragma unroll
        for (int q = 0; q < 4; q++) {
            int id = tid + 256 * q, kk = id >> 5, e = (id & 31) << 2;
            *(float4*)&Bs[kk][e] = *(const float4*)(W + (size_t)(k0 + kk) * CB_DIM + e);
        }
        __syncthreads();
        #pragma unroll 8
        for (int kk = 0; kk < PJ_BK; kk++) {
            ull a[4];
            a[0] = *(const ull*)&As[kk][tr*8 + 0];
            a[1] = *(const ull*)&As[kk][tr*8 + 2];
            a[2] = *(const ull*)&As[kk][tr*8 + 4];
            a[3] = *(const ull*)&As[kk][tr*8 + 6];
            float4 b0 = *(float4*)&Bs[kk][tc*8];
            float4 b1 = *(float4*)&Bs[kk][tc*8 + 4];
            ull bb[8];
            PACKDUP(bb[0], b0.x); PACKDUP(bb[1], b0.y);
            PACKDUP(bb[2], b0.z); PACKDUP(bb[3], b0.w);
            PACKDUP(bb[4], b1.x); PACKDUP(bb[5], b1.y);
            PACKDUP(bb[6], b1.z); PACKDUP(bb[7], b1.w);
            #pragma unroll
            for (int p = 0; p < 4; p++)
                #pragma unroll
                for (int j = 0; j < 8; j++)
                    FMA2(acc[p][j], a[p], bb[j]);
        }
        __syncthreads();
    }

    // ---- fused epilogue ----
    float* rs   = &As[0][0];
    float* invs = rs + 2048;

    #pragma unroll
    for (int p = 0; p < 4; p++) {
        float slo = 0.0f, shi = 0.0f;
        #pragma unroll
        for (int j = 0; j < 8; j++) {
            float lo, hi; UNPACK2(lo, hi, acc[p][j]);
            slo += lo * lo; shi += hi * hi;
        }
        rs[(tr*8 + 2*p)     * 16 + tc] = slo;
        rs[(tr*8 + 2*p + 1) * 16 + tc] = shi;
    }
    __syncthreads();
    if (tid < 128) {
        float s = 0.0f;
        #pragma unroll
        for (int c = 0; c < 16; c++) s += rs[tid * 16 + c];
        invs[tid] = 1.0f / fmaxf(sqrtf(s), 1e-12f);
    }
    __syncthreads();

    int t = blockIdx.x;
    float alsq[8];
    #pragma unroll
    for (int i = 0; i < 8; i++) alsq[i] = 0.0f;

    #pragma unroll
    for (int p = 0; p < 4; p++) {
        int rl0 = tr*8 + 2*p, rl1 = rl0 + 1;
        float i0 = invs[rl0], i1 = invs[rl1];
        float lov[8], hiv[8];
        #pragma unroll
        for (int j = 0; j < 8; j++) {
            float lo, hi; UNPACK2(lo, hi, acc[p][j]);
            lov[j] = lo * i0; hiv[j] = hi * i1;
        }
        *(float4*)(g_nx + (size_t)(rowbase+rl0)*CB_DIM + tc*8)     = make_float4(lov[0],lov[1],lov[2],lov[3]);
        *(float4*)(g_nx + (size_t)(rowbase+rl0)*CB_DIM + tc*8 + 4) = make_float4(lov[4],lov[5],lov[6],lov[7]);
        *(float4*)(g_nx + (size_t)(rowbase+rl1)*CB_DIM + tc*8)     = make_float4(hiv[0],hiv[1],hiv[2],hiv[3]);
        *(float4*)(g_nx + (size_t)(rowbase+rl1)*CB_DIM + tc*8 + 4) = make_float4(hiv[4],hiv[5],hiv[6],hiv[7]);
        #pragma unroll
        for (int j = 0; j < 8; j++) {
            #pragma unroll
            for (int half = 0; half < 2; half++) {
                int r = half ? rl1 : rl0;
                float val = half ? hiv[j] : lov[j];
                __nv_bfloat16 h = __float2bfloat16(val);
                __nv_bfloat16 l = __float2bfloat16(val - __bfloat162float(h));
                float lf = __bfloat162float(l);
                alsq[2*p + half] += lf * lf;
                int k = tc*8 + j;
                int w = r >> 4, rr = r & 15, gg = rr & 7, half_r = rr >> 3;
                int ks = k >> 4, rk = k & 15;
                int q = (rk & 7) >> 1, e = rk & 1, kh = rk >> 3;
                int slot = half_r + 2*kh;
                size_t fidx = ((size_t)t * 16384) + (size_t)(((w*8 + ks)*32 + gg*4 + q)*8 + slot*2 + e);
                g_afh[fidx] = h;
            }
        }
    }
    #pragma unroll
    for (int p = 0; p < 4; p++) {
        rs[(tr*8 + 2*p)     * 16 + tc] = alsq[2*p];
        rs[(tr*8 + 2*p + 1) * 16 + tc] = alsq[2*p + 1];
    }
    __syncthreads();
    if (tid < 128) {
        float s = 0.0f;
        #pragma unroll
        for (int c = 0; c < 16; c++) s += rs[tid * 16 + c];
        g_nal[rowbase + tid] = sqrtf(s);
    }
}

// ---------------------------------------------------------------------------
// Shared MMA helper
// ---------------------------------------------------------------------------
__device__ __forceinline__ void mma16816(float c[4], const uint32_t a[4],
                                         const uint32_t b0, const uint32_t b1) {
    asm volatile(
        "mma.sync.aligned.m16n8k16.row.col.f32.bf16.bf16.f32 "
        "{%0,%1,%2,%3}, {%4,%5,%6,%7}, {%8,%9}, {%0,%1,%2,%3};"
        : "+f"(c[0]), "+f"(c[1]), "+f"(c[2]), "+f"(c[3])
        : "r"(a[0]), "r"(a[1]), "r"(a[2]), "r"(a[3]), "r"(b0), "r"(b1));
}

// ---------------------------------------------------------------------------
// Kernel 3 (phase A): hi*hi-only scorer over all rows + certified flagging.
// ---------------------------------------------------------------------------
#define BUFA 16640

__device__ __forceinline__ void copy_bh_tile(uint32_t dst, int ct, int tid) {
    const char* sh = (const char*)g_bfh + (size_t)ct * 16384;
    const char* hh = (const char*)g_h2  + (size_t)ct * 256;
    for (int i = tid; i < 1040; i += 256) {
        if (i < 1024) CPA16(dst + i * 16,                  sh + i * 16);
        else          CPA16(dst + 16384 + (i - 1024) * 16, hh + (i - 1024) * 16);
    }
    CP_COMMIT();
}

__global__ __launch_bounds__(256, 2) void rpq_scoreA(float* __restrict__ out) {
    extern __shared__ char smem[];
    uint32_t sb = smem_u32(smem);
    int tid  = threadIdx.x;
    int warp = tid >> 5;
    int lane = tid & 31;
    int g    = lane >> 2;
    int t2   = (lane & 3) * 2;
    int rowbase = blockIdx.x * 128;

    uint32_t ah[8][4];
    {
        const uint4* ph = (const uint4*)g_afh + (size_t)blockIdx.x * 2048 + warp * 256 + lane;
        #pragma unroll
        for (int ks = 0; ks < 8; ks++) {
            uint4 v = ph[ks * 32];
            ah[ks][0] = v.x; ah[ks][1] = v.y; ah[ks][2] = v.z; ah[ks][3] = v.w;
        }
    }

    copy_bh_tile(sb, 0, tid);

    float best0 = -FLT_MAX, sb0 = -FLT_MAX, best1 = -FLT_MAX, sb1 = -FLT_MAX;
    int   i0 = 0, i1 = 0;

    for (int ct = 0; ct < 128; ct++) {
        int buf = ct & 1;
        __syncthreads();
        if (ct + 1 < 128) { copy_bh_tile(sb + (buf ^ 1) * BUFA, ct + 1, tid); CP_WAIT1(); }
        else              { CP_WAIT0(); }
        __syncthreads();

        uint32_t bbase = sb + buf * BUFA;
        float c[8][4];
        #pragma unroll
        for (int f = 0; f < 8; f++)
            #pragma unroll
            for (int qq = 0; qq < 4; qq++) c[f][qq] = 0.0f;

        #pragma unroll
        for (int ks = 0; ks < 8; ks++) {
            #pragma unroll
            for (int f = 0; f < 8; f++) {
                uint32_t off = ((ks * 8 + f) * 32 + lane) * 8;
                uint32_t bh0, bh1;
                asm volatile("ld.shared.v2.b32 {%0,%1}, [%2];"
                             : "=r"(bh0), "=r"(bh1) : "r"(bbase + off));
                mma16816(c[f], ah[ks], bh0, bh1);
            }
        }

        const float* h2s = (const float*)(smem + buf * BUFA + 16384);
        int cb0 = ct * 64;
        #pragma unroll
        for (int f = 0; f < 8; f++) {
            float h0 = h2s[f * 8 + t2], h1 = h2s[f * 8 + t2 + 1];
            int id0 = cb0 + f * 8 + t2, id1 = id0 + 1;
            float s;
            s = c[f][0] - h0;
            if (s > best0) { sb0 = best0; best0 = s; i0 = id0; } else if (s > sb0) sb0 = s;
            s = c[f][1] - h1;
            if (s > best0) { sb0 = best0; best0 = s; i0 = id1; } else if (s > sb0) sb0 = s;
            s = c[f][2] - h0;
            if (s > best1) { sb1 = best1; best1 = s; i1 = id0; } else if (s > sb1) sb1 = s;
            s = c[f][3] - h1;
            if (s > best1) { sb1 = best1; best1 = s; i1 = id1; } else if (s > sb1) sb1 = s;
        }
    }

    #pragma unroll
    for (int off = 1; off <= 2; off <<= 1) {
        float ob, osb; int oi;
        ob  = __shfl_xor_sync(0xffffffffu, best0, off);
        osb = __shfl_xor_sync(0xffffffffu, sb0,   off);
        oi  = __shfl_xor_sync(0xffffffffu, i0,    off);
        if (ob > best0) { sb0 = fmaxf(best0, osb); best0 = ob; i0 = oi; }
        else { if (ob == best0 && oi < i0) i0 = oi; sb0 = fmaxf(sb0, ob); }
        ob  = __shfl_xor_sync(0xffffffffu, best1, off);
        osb = __shfl_xor_sync(0xffffffffu, sb1,   off);
        oi  = __shfl_xor_sync(0xffffffffu, i1,    off);
        if (ob > best1) { sb1 = fmaxf(best1, osb); best1 = ob; i1 = oi; }
        else { if (ob == best1 && oi < i1) i1 = oi; sb1 = fmaxf(sb1, ob); }
    }

    if ((lane & 3) == 0) {
        int row0 = rowbase + (warp << 4) + g;
        int row1 = row0 + 8;
        out[row0] = (float)i0;
        out[row1] = (float)i1;
        float mbl  = __int_as_float(g_mbl) * 1.002f + 1e-6f;
        float nal0 = g_nal[row0] * 1.002f + 1e-6f;
        float nal1 = g_nal[row1] * 1.002f + 1e-6f;
        float thr0 = 2.0f * (nal0 * (1.001f + 2.0f * mbl) + 1.001f * mbl + 2e-5f);
        float thr1 = 2.0f * (nal1 * (1.001f + 2.0f * mbl) + 1.001f * mbl + 2e-5f);
        if (best0 - sb0 < thr0) { int s = atomicAdd(&g_nflag, 1); g_flag[s] = row0; }
        if (best1 - sb1 < thr1) { int s = atomicAdd(&g_nflag, 1); g_flag[s] = row1; }
    }
}

// ---------------------------------------------------------------------------
// Kernel 4 (phase B): 3-product rescorer, CHUNKED for parallelism.
// Work item = (flagged-row tile, codebook chunk of 2048 codes). Each item
// writes per-row (best, second, idx) partials; combine kernel merges.
// ---------------------------------------------------------------------------
#define BUFB 33024
#define SMEM_B2 66048

__device__ __forceinline__ void copy_b_tile(uint32_t dst, int ct, int tid) {
    const char* sh = (const char*)g_bfh + (size_t)ct * 16384;
    const char* sl = (const char*)g_bfl + (size_t)ct * 16384;
    const char* hh = (const char*)g_h2  + (size_t)ct * 256;
    for (int i = tid; i < 2064; i += 256) {
        if (i < 1024)       CPA16(dst + i * 16,                  sh + i * 16);
        else if (i < 2048)  CPA16(dst + 16384 + (i - 1024) * 16, sl + (i - 1024) * 16);
        else                CPA16(dst + 32768 + (i - 2048) * 16, hh + (i - 2048) * 16);
    }
    CP_COMMIT();
}

__device__ __forceinline__ uint32_t packsplit(float v0, float v1, uint32_t* lo) {
    __nv_bfloat16 h0 = __float2bfloat16(v0), h1 = __float2bfloat16(v1);
    __nv_bfloat16 l0 = __float2bfloat16(v0 - __bfloat162float(h0));
    __nv_bfloat16 l1 = __float2bfloat16(v1 - __bfloat162float(h1));
    __nv_bfloat162 hp = __halves2bfloat162(h0, h1);
    __nv_bfloat162 lp = __halves2bfloat162(l0, l1);
    *lo = *reinterpret_cast<uint32_t*>(&lp);
    return *reinterpret_cast<uint32_t*>(&hp);
}

__global__ __launch_bounds__(256, 2) void rpq_scoreB() {
    extern __shared__ char smem[];
    __shared__ int sidx[128];
    uint32_t sb = smem_u32(smem);
    int tid  = threadIdx.x;
    int warp = tid >> 5;
    int lane = tid & 31;
    int g    = lane >> 2;
    int t2   = (lane & 3) * 2;
    int nf = g_nflag;
    int ntiles = (nf + 127) >> 7;
    int nwork = ntiles * 4;

    for (int w = blockIdx.x; w < nwork; w += gridDim.x) {
        int tile = w >> 2, chunk = w & 3;
        int base = tile * 128;
        int cnt = nf - base; if (cnt > 128) cnt = 128;
        __syncthreads();   // prior iteration's smem fully consumed
        if (tid < 128) sidx[tid] = g_flag[base + (tid < cnt ? tid : 0)];
        __syncthreads();

        // stage gathered rows as f32, stride 129 (bank-spread)
        float* stg = (float*)smem;
        for (int i = tid; i < 4096; i += 256) {
            int r = i >> 5, c4 = (i & 31) << 2;
            float4 v = *(const float4*)&g_nx[(size_t)sidx[r] * CB_DIM + c4];
            float* d = stg + r * 129 + c4;
            d[0] = v.x; d[1] = v.y; d[2] = v.z; d[3] = v.w;
        }
        __syncthreads();

        // extract A fragments (hi+lo) to registers
        uint32_t ah[8][4], al[8][4];
        int r0 = (warp << 4) + g;
        #pragma unroll
        for (int ks = 0; ks < 8; ks++) {
            int kb = ks * 16 + t2;
            const float* p00 = stg + r0 * 129 + kb;
            const float* p10 = stg + (r0 + 8) * 129 + kb;
            ah[ks][0] = packsplit(p00[0], p00[1], &al[ks][0]);
            ah[ks][1] = packsplit(p10[0], p10[1], &al[ks][1]);
            ah[ks][2] = packsplit(p00[8], p00[9], &al[ks][2]);
            ah[ks][3] = packsplit(p10[8], p10[9], &al[ks][3]);
        }
        __syncthreads();   // staging reads done before B tiles overwrite

        copy_b_tile(sb, chunk * 32, tid);

        float best0 = -FLT_MAX, sb0 = -FLT_MAX, best1 = -FLT_MAX, sb1 = -FLT_MAX;
        int   i0 = 0, i1 = 0;

        for (int ctl = 0; ctl < 32; ctl++) {
            int ct = chunk * 32 + ctl;
            int buf = ctl & 1;
            __syncthreads();
            if (ctl + 1 < 32) { copy_b_tile(sb + (buf ^ 1) * BUFB, ct + 1, tid); CP_WAIT1(); }
            else              { CP_WAIT0(); }
            __syncthreads();

            uint32_t bbase = sb + buf * BUFB;
            float c[8][4];
            #pragma unroll
            for (int f = 0; f < 8; f++)
                #pragma unroll
                for (int qq = 0; qq < 4; qq++) c[f][qq] = 0.0f;

            #pragma unroll
            for (int ks = 0; ks < 8; ks++) {
                #pragma unroll
                for (int f = 0; f < 8; f++) {
                    uint32_t off = ((ks * 8 + f) * 32 + lane) * 8;
                    uint32_t bh0, bh1, bl0, bl1;
                    asm volatile("ld.shared.v2.b32 {%0,%1}, [%2];"
                                 : "=r"(bh0), "=r"(bh1) : "r"(bbase + off));
                    asm volatile("ld.shared.v2.b32 {%0,%1}, [%2];"
                                 : "=r"(bl0), "=r"(bl1) : "r"(bbase + 16384 + off));
                    mma16816(c[f], ah[ks], bh0, bh1);
                    mma16816(c[f], ah[ks], bl0, bl1);
                    mma16816(c[f], al[ks], bh0, bh1);
                }
            }

            const float* h2s = (const float*)(smem + buf * BUFB + 32768);
            int cb0 = ct * 64;
            #pragma unroll
            for (int f = 0; f < 8; f++) {
                float h0 = h2s[f * 8 + t2], h1 = h2s[f * 8 + t2 + 1];
                int id0 = cb0 + f * 8 + t2, id1 = id0 + 1;
                float s;
                s = c[f][0] - h0;
                if (s > best0) { sb0 = best0; best0 = s; i0 = id0; } else if (s > sb0) sb0 = s;
                s = c[f][1] - h1;
                if (s > best0) { sb0 = best0; best0 = s; i0 = id1; } else if (s > sb0) sb0 = s;
                s = c[f][2] - h0;
                if (s > best1) { sb1 = best1; best1 = s; i1 = id0; } else if (s > sb1) sb1 = s;
                s = c[f][3] - h1;
                if (s > best1) { sb1 = best1; best1 = s; i1 = id1; } else if (s > sb1) sb1 = s;
            }
        }

        #pragma unroll
        for (int off = 1; off <= 2; off <<= 1) {
            float ob, osb; int oi;
            ob  = __shfl_xor_sync(0xffffffffu, best0, off);
            osb = __shfl_xor_sync(0xffffffffu, sb0,   off);
            oi  = __shfl_xor_sync(0xffffffffu, i0,    off);
            if (ob > best0) { sb0 = fmaxf(best0, osb); best0 = ob; i0 = oi; }
            else { if (ob == best0 && oi < i0) i0 = oi; sb0 = fmaxf(sb0, ob); }
            ob  = __shfl_xor_sync(0xffffffffu, best1, off);
            osb = __shfl_xor_sync(0xffffffffu, sb1,   off);
            oi  = __shfl_xor_sync(0xffffffffu, i1,    off);
            if (ob > best1) { sb1 = fmaxf(best1, osb); best1 = ob; i1 = oi; }
            else { if (ob == best1 && oi < i1) i1 = oi; sb1 = fmaxf(sb1, ob); }
        }

        if ((lane & 3) == 0) {
            int pos0 = (warp << 4) + g, pos1 = pos0 + 8;
            size_t ob = ((size_t)(tile * 4 + chunk)) * 128;
            g_pb_b[ob + pos0] = best0; g_pb_s[ob + pos0] = sb0; g_pb_i[ob + pos0] = i0;
            g_pb_b[ob + pos1] = best1; g_pb_s[ob + pos1] = sb1; g_pb_i[ob + pos1] = i1;
        }
    }
}

// ---------------------------------------------------------------------------
// Kernel 5: combine phase-B chunk partials; certify; flag for exact pass.
// ---------------------------------------------------------------------------
__global__ void rpq_combineB(float* __restrict__ out) {
    int p = blockIdx.x * blockDim.x + threadIdx.x;
    int nf = g_nflag;
    if (p >= nf) return;
    int tile = p >> 7, r = p & 127;
    size_t ob = ((size_t)tile * 4) * 128 + r;
    float b = -FLT_MAX, s = -FLT_MAX; int i = 0x7fffffff;
    #pragma unroll
    for (int c = 0; c < 4; c++) {
        float bc = g_pb_b[ob + (size_t)c * 128];
        float sc = g_pb_s[ob + (size_t)c * 128];
        int   ic = g_pb_i[ob + (size_t)c * 128];
        if (bc > b) { s = fmaxf(b, sc); b = bc; i = ic; }
        else        { if (bc == b && ic < i) i = ic; s = fmaxf(s, bc); }
    }
    int row = g_flag[p];
    out[row] = (float)i;
    if (b - s < GAP_THR_B) { int t = atomicAdd(&g_nflagB, 1); g_flagB[t] = row; }
}

// ---------------------------------------------------------------------------
// Kernel 6 (phase C): exact fp32 rescore of phase-B flagged rows.
// ---------------------------------------------------------------------------
__global__ __launch_bounds__(256) void rpq_exactB(float* __restrict__ out) {
    __shared__ float xr[CB_DIM];
    __shared__ float rb[256];
    __shared__ int   ri[256];
    int tid = threadIdx.x;
    int nf = g_nflagB;
    for (int fi = blockIdx.x; fi < nf; fi += gridDim.x) {
        int row = g_flagB[fi];
        if (tid < CB_DIM) xr[tid] = g_nx[(size_t)row * CB_DIM + tid];
        __syncthreads();
        float best = -FLT_MAX; int bi = 0;
        for (int c = tid; c < CB_SIZE; c += 256) {
            const float* cbr = g_ncb + (size_t)c * CB_DIM;
            float acc = 0.0f;
            #pragma unroll
            for (int k = 0; k < CB_DIM; k += 4) {
                float4 v = *(const float4*)&cbr[k];
                acc = fmaf(v.x, xr[k],     acc);
                acc = fmaf(v.y, xr[k + 1], acc);
                acc = fmaf(v.z, xr[k + 2], acc);
                acc = fmaf(v.w, xr[k + 3], acc);
            }
            float s = acc - g_h2[c];
            if (s > best) { best = s; bi = c; }
        }
        rb[tid] = best; ri[tid] = bi;
        __syncthreads();
        for (int off = 128; off > 0; off >>= 1) {
            if (tid < off) {
                float o = rb[tid + off]; int oi = ri[tid + off];
                if (o > rb[tid] || (o == rb[tid] && oi < ri[tid])) { rb[tid] = o; ri[tid] = oi; }
            }
            __syncthreads();
        }
        if (tid == 0) out[row] = (float)ri[0];
        __syncthreads();
    }
}

// ---------------------------------------------------------------------------
// Launch
// ---------------------------------------------------------------------------
extern "C" void kernel_launch(void* const* d_in, const int* in_sizes, int n_in,
                              void* d_out, int out_size) {
    const float* x  = nullptr;
    const float* W  = nullptr;
    const float* cb = nullptr;
    for (int i = 0; i < n_in; i++) {
        long long s = in_sizes[i];
        if      (s == (long long)NROWS * IN_DIM   || s == (long long)NROWS * IN_DIM * 4)
            x  = (const float*)d_in[i];
        else if (s == (long long)IN_DIM * CB_DIM  || s == (long long)IN_DIM * CB_DIM * 4)
            W  = (const float*)d_in[i];
        else if (s == (long long)CB_SIZE * CB_DIM || s == (long long)CB_SIZE * CB_DIM * 4)
            cb = (const float*)d_in[i];
    }
    if (!x || !W || !cb) {
        x  = (const float*)d_in[0];
        W  = (const float*)d_in[1];
        cb = (const float*)d_in[2];
    }
    float* out = (float*)d_out;

    cudaFuncSetAttribute(rpq_scoreB,
                         cudaFuncAttributeMaxDynamicSharedMemorySize, SMEM_B2);

    rpq_prep_cb   <<<CB_SIZE / 8, 256>>>(cb);
    rpq_proj_fused<<<NROWS / 128, 256>>>(x, W);
    rpq_scoreA    <<<NROWS / 128, 256, 2 * BUFA>>>(out);
    rpq_scoreB    <<<296, 256, SMEM_B2>>>();          // 2 blocks/SM, chip-filling
    rpq_combineB  <<<NROWS / 256, 256>>>(out);
    rpq_exactB    <<<256, 256>>>(out);
}